// round 13
// baseline (speedup 1.0000x reference)
#include <cuda_runtime.h>
#include <cuda_bf16.h>

#define CCH   256
#define HH    360
#define WW    360
#define NPTS  1024
#define CPB   16
#define NPAIR (CPB / 2)   // 8 center pairs per block

typedef unsigned long long ull;

// Scratch: a1[m][k] = f1 @ w3 ; a2p[n][k] = b3[k] - (f2 @ w3)[n][k]
__device__ float g_a1[NPTS * 32];
__device__ float g_a2p[NPTS * 32];

#define FFMA2(acc, x, w) \
    asm("fma.rn.f32x2 %0, %1, %2, %0;" : "+l"(acc) : "l"(x), "l"(w))
#define FADD2(d, a, b) \
    asm("add.rn.f32x2 %0, %1, %2;" : "=l"(d) : "l"(a), "l"(b))

#define CP_ASYNC16(dst_u32, src_ptr) \
    asm volatile("cp.async.cg.shared.global [%0], [%1], 16;" \
                 :: "r"(dst_u32), "l"(src_ptr) : "memory")
#define CP_COMMIT() asm volatile("cp.async.commit_group;" ::: "memory")
#define CP_WAIT1()  asm volatile("cp.async.wait_group 1;" ::: "memory")
#define CP_WAIT0()  asm volatile("cp.async.wait_group 0;" ::: "memory")

__device__ __forceinline__ ull pack2(float a, float b) {
    ull r;
    asm("mov.b64 %0, {%1, %2};" : "=l"(r) : "f"(a), "f"(b));
    return r;
}
__device__ __forceinline__ float2 unpack2(ull v) {
    float2 f;
    asm("mov.b64 {%0, %1}, %2;" : "=f"(f.x), "=f"(f.y) : "l"(v));
    return f;
}

// ---------------------------------------------------------------------------
// Kernel 1: gather + 256->256->128 MLP (relu) + @w3 projection (b3 folded).
// 16 centers per block, 512 threads, 128 blocks, split-K partial sums.
// Layers 1-2 weights streamed via cp.async double buffering.
// BUG FIX vs r12: layer 1 needs 32 chunks (w1 = 256KB = 32 x 8KB), not 16 —
// r11/r12 accumulated only half the layer-1 channels (rel_err 0.67).
// Layer 2 stays at 16 chunks (w2 = 128KB = 16 x 8KB) — verified correct.
// Shared memory (48KB, overlaid by liveness):
//   smemA: xs2[8][256]            -> w3s[128*32]   (layer1 epilogue on)
//   smemB: part1 (l1 epilogue)    -> wbuf2[2][2048] (l2 loop)
//                                 -> part2[8][128]|h2p[8][128] (l2 epilogue)
//   smemC: wbuf1[2][2048] (l1 loop) -> h1p[8][256]  (l1 epilogue on)
// ---------------------------------------------------------------------------
__global__ __launch_bounds__(512) void project_kernel(
    const float* __restrict__ feature,
    const int*   __restrict__ idx1,
    const int*   __restrict__ idx2,
    const float* __restrict__ w1, const float* __restrict__ b1,
    const float* __restrict__ w2, const float* __restrict__ b2,
    const float* __restrict__ w3, const float* __restrict__ b3)
{
    __shared__ float2 smemA[NPAIR * 256];   // 16KB
    __shared__ float2 smemB[NPAIR * 256];   // 16KB
    __shared__ float2 smemC[NPAIR * 256];   // 16KB

    float2 (*xs2)[256] = (float2 (*)[256])smemA;
    float*  w3s        = (float*)smemA;
    float2 (*part1)[256] = (float2 (*)[256])smemB;
    float*  wbuf2      = (float*)smemB;      // layer2 loop: [2][2048] floats
    float2* part2      = smemB;              // [8][128] float2 = 8KB
    float2 (*h2p)[128] = (float2 (*)[128])(smemB + 1024); // 8KB
    float*  wbuf1      = (float*)smemC;      // layer1 loop: [2][2048] floats
    float2 (*h1p)[256] = (float2 (*)[256])smemC;

    const unsigned wbuf1_u32 = (unsigned)__cvta_generic_to_shared(wbuf1);
    const unsigned wbuf2_u32 = (unsigned)__cvta_generic_to_shared(wbuf2);

    const int tid = threadIdx.x;
    const int g0  = blockIdx.x * CPB;
    const bool frame2 = (g0 >= NPTS);
    const int* __restrict__ idx = frame2 ? idx2 : idx1;
    const int  i0 = frame2 ? (g0 - NPTS) : g0;

    const float4* w1v = (const float4*)w1;
    const float4* w2v = (const float4*)w2;
    const int ct     = tid;
    const int chalf  = (ct >> 8);            // 0 or 1
    const int clocal = ct & 255;

    // stage layer1 chunk 0 early (into smemC, untouched by gather)
    {
        const float4* src = w1v + (chalf ? (8192 + clocal) : clocal);
        CP_ASYNC16(wbuf1_u32 + ct * 16, src);
        CP_COMMIT();
    }

    // ---- gather: 16 centers x 256 channels = 4096 loads over 512 threads
    #pragma unroll
    for (int i = 0; i < 8; i++) {
        int e  = tid + i * 512;
        int t  = e >> 8;
        int ch = e & 255;
        int b  = __ldg(&idx[i0 + t]);
        int hh = __ldg(&idx[NPTS + i0 + t]);
        int ww = __ldg(&idx[2 * NPTS + i0 + t]);
        long off = (((long)b * CCH + ch) * HH + hh) * (long)WW + ww;
        ((float*)&xs2[t >> 1][ch])[t & 1] = __ldg(&feature[off]);
    }
    __syncthreads();

    // ---- layer 1: h1 = relu(x @ w1 + b1)
    // thread (j = tid&255, h = tid>>8): output col j, channel half h.
    // 32 chunks of 4 channels per half (8KB/chunk), double buffered.
    {
        const int j = tid & 255;
        const int h = tid >> 8;
        const int cbase = h * 128;
        ull acc[NPAIR];
        {
            ull init;
            if (h) init = 0ULL;
            else { float bb = b1[j]; init = pack2(bb, bb); }
            #pragma unroll
            for (int p = 0; p < NPAIR; p++) acc[p] = init;
        }
        #pragma unroll 1
        for (int kk = 0; kk < 32; kk++) {
            if (kk < 31) {
                const float4* src = w1v + (chalf ? (8192 + (kk + 1) * 256 + clocal)
                                                 : ((kk + 1) * 256 + clocal));
                CP_ASYNC16(wbuf1_u32 + ((kk + 1) & 1) * 8192 + ct * 16, src);
                CP_COMMIT();
                CP_WAIT1();      // chunk kk complete
            } else {
                CP_WAIT0();
            }
            __syncthreads();     // chunk kk visible to all
            const float* wb = wbuf1 + (kk & 1) * 2048 + h * 1024;
            float v0 = wb[j];
            float v1 = wb[256 + j];
            float v2 = wb[512 + j];
            float v3 = wb[768 + j];
            ull p0 = pack2(v0, v0), p1 = pack2(v1, v1);
            ull p2 = pack2(v2, v2), p3 = pack2(v3, v3);
            const int c = cbase + kk * 4;
            #pragma unroll
            for (int p = 0; p < NPAIR; p++) {
                ulonglong2 qa = *(const ulonglong2*)&xs2[p][c];
                ulonglong2 qb = *(const ulonglong2*)&xs2[p][c + 2];
                FFMA2(acc[p], qa.x, p0);
                FFMA2(acc[p], qa.y, p1);
                FFMA2(acc[p], qb.x, p2);
                FFMA2(acc[p], qb.y, p3);
            }
            __syncthreads();     // all reads of buf kk done before next
                                 // iteration's cp.async overwrites it
        }
        if (h) {
            #pragma unroll
            for (int p = 0; p < NPAIR; p++)
                part1[p][j] = unpack2(acc[p]);
        }
        __syncthreads();   // xs2 dead; part1 ready; wbuf1 reads all done
        if (!h) {
            #pragma unroll
            for (int p = 0; p < NPAIR; p++) {
                float2 f = unpack2(acc[p]);
                float2 g = part1[p][j];
                h1p[p][j] = make_float2(fmaxf(f.x + g.x, 0.0f),
                                        fmaxf(f.y + g.y, 0.0f));
            }
        } else {
            // h==1 threads stage w3 into the freed xs2 region
            const float4* src = (const float4*)w3;
            float4* dst = (float4*)w3s;
            int l = tid - 256;
            #pragma unroll
            for (int i = 0; i < 4; i++) dst[l + i * 256] = src[l + i * 256];
        }
    }
    __syncthreads();   // part1 consumed; smemB free for wbuf2

    // ---- layer 2: h2 = relu(h1 @ w2 + b2)
    // thread (j2 = tid&127, q = tid>>7): qc = channel half, qp = pair half.
    // 16 chunks of 8 channels per half (8KB/chunk), double buffered (smemB).
    {
        const int j2 = tid & 127;
        const int q  = tid >> 7;
        const int qc = q & 1;
        const int qp = q >> 1;
        const int cbase = qc * 128;
        const int pb = qp * 4;
        ull acc[4];
        {
            ull init;
            if (qc) init = 0ULL;
            else { float bb = b2[j2]; init = pack2(bb, bb); }
            #pragma unroll
            for (int u = 0; u < 4; u++) acc[u] = init;
        }
        // stage chunk 0
        {
            const float4* src = w2v + (chalf ? (4096 + clocal) : clocal);
            CP_ASYNC16(wbuf2_u32 + ct * 16, src);
            CP_COMMIT();
        }
        #pragma unroll 1
        for (int kk = 0; kk < 16; kk++) {
            if (kk < 15) {
                const float4* src = w2v + (chalf ? (4096 + (kk + 1) * 256 + clocal)
                                                 : ((kk + 1) * 256 + clocal));
                CP_ASYNC16(wbuf2_u32 + ((kk + 1) & 1) * 8192 + ct * 16, src);
                CP_COMMIT();
                CP_WAIT1();
            } else {
                CP_WAIT0();
            }
            __syncthreads();
            const float* wb = wbuf2 + (kk & 1) * 2048 + qc * 1024;
            const int cg = cbase + kk * 8;
            #pragma unroll
            for (int s = 0; s < 2; s++) {           // two 4-channel substeps
                const int cl = s * 4;
                float v0 = wb[(cl + 0) * 128 + j2];
                float v1 = wb[(cl + 1) * 128 + j2];
                float v2 = wb[(cl + 2) * 128 + j2];
                float v3 = wb[(cl + 3) * 128 + j2];
                ull p0 = pack2(v0, v0), p1 = pack2(v1, v1);
                ull p2 = pack2(v2, v2), p3 = pack2(v3, v3);
                const int c = cg + cl;
                #pragma unroll
                for (int u = 0; u < 4; u++) {
                    int p = pb + u;
                    ulonglong2 qa = *(const ulonglong2*)&h1p[p][c];
                    ulonglong2 qb = *(const ulonglong2*)&h1p[p][c + 2];
                    FFMA2(acc[u], qa.x, p0);
                    FFMA2(acc[u], qa.y, p1);
                    FFMA2(acc[u], qb.x, p2);
                    FFMA2(acc[u], qb.y, p3);
                }
            }
            __syncthreads();     // buffer-reuse barrier (same as layer 1)
        }
        if (qc) {
            #pragma unroll
            for (int u = 0; u < 4; u++)
                part2[(qp * 4 + u) * 128 + j2] = unpack2(acc[u]);
        }
        __syncthreads();   // part2 ready; wbuf2 fully consumed
        if (!qc) {
            #pragma unroll
            for (int u = 0; u < 4; u++) {
                float2 f = unpack2(acc[u]);
                float2 g = part2[(qp * 4 + u) * 128 + j2];
                h2p[pb + u][j2] = make_float2(fmaxf(f.x + g.x, 0.0f),
                                              fmaxf(f.y + g.y, 0.0f));
            }
        }
    }
    __syncthreads();

    // ---- layer 3 (projection): a = h2 @ w3, b3 folded for frame 2.
    // 16 warps, warp w -> center w; lane k -> output dim k.
    {
        const int w = tid >> 5;       // 0..15 = center
        const int k = tid & 31;
        const int p = w >> 1;
        const int hl = w & 1;
        float acc0 = 0.0f, acc1 = 0.0f, acc2 = 0.0f, acc3 = 0.0f;
        #pragma unroll 8
        for (int d = 0; d < 128; d += 4) {
            float hv0 = ((const float*)&h2p[p][d + 0])[hl];
            float hv1 = ((const float*)&h2p[p][d + 1])[hl];
            float hv2 = ((const float*)&h2p[p][d + 2])[hl];
            float hv3 = ((const float*)&h2p[p][d + 3])[hl];
            acc0 = fmaf(hv0, w3s[(d + 0) * 32 + k], acc0);
            acc1 = fmaf(hv1, w3s[(d + 1) * 32 + k], acc1);
            acc2 = fmaf(hv2, w3s[(d + 2) * 32 + k], acc2);
            acc3 = fmaf(hv3, w3s[(d + 3) * 32 + k], acc3);
        }
        float r = (acc0 + acc1) + (acc2 + acc3);
        int gg = g0 + w;
        if (!frame2) {
            g_a1[gg * 32 + k] = r;
        } else {
            g_a2p[(gg - NPTS) * 32 + k] = b3[k] - r;
        }
    }
}

// ---------------------------------------------------------------------------
// Kernel 2: out[m,n] = b4 + sum_k relu(a1[m,k] + a2p[n,k]) * w4[k]
// 256 threads (each owns one n), m-tile 16, grid (4, 64) = 256 CTAs.
// Byte-identical to round-10 best (9.5us).
// ---------------------------------------------------------------------------
__global__ __launch_bounds__(256) void pair_kernel(
    const float* __restrict__ w4,
    const float* __restrict__ b4,
    float*       __restrict__ out)
{
    __shared__ float a1s[16 * 32];   // 2KB
    __shared__ float2 w4s[16];       // 128B: packed (w4[2i], w4[2i+1]) pairs

    const int tid = threadIdx.x;
    const int n   = blockIdx.x * 256 + tid;
    const int m0  = blockIdx.y * 16;

    // stage a1 tile (16 x 32 = 512 floats) via float4
    if (tid < 128)
        ((float4*)a1s)[tid] = ((const float4*)(g_a1 + m0 * 32))[tid];
    // stage w4 pairs
    if (tid < 16)
        w4s[tid] = ((const float2*)w4)[tid];

    // a2p row packed as 16 f32x2 pairs (per-thread, reused for all 16 m)
    ull a2p[16];
    {
        const float4* ar = (const float4*)(g_a2p + (long)n * 32);
        #pragma unroll
        for (int v = 0; v < 8; v++) {
            float4 a = ar[v];
            a2p[2 * v]     = pack2(a.x, a.y);
            a2p[2 * v + 1] = pack2(a.z, a.w);
        }
    }
    const float bias = b4[0];
    __syncthreads();

    #pragma unroll 2
    for (int m = 0; m < 16; m++) {
        const ulonglong2* ap = (const ulonglong2*)&a1s[m * 32];
        const ulonglong2* wp = (const ulonglong2*)w4s;
        ull acc0 = pack2(bias, 0.0f), acc1 = 0ULL;
        #pragma unroll
        for (int v = 0; v < 8; v++) {      // 8 chunks x 4 dims = 32 dims
            ulonglong2 qa = ap[v];         // a1 dims 4v .. 4v+3 (broadcast)
            ulonglong2 wv = wp[v];         // w4 dims 4v .. 4v+3 (broadcast)
            ull s0, s1;
            FADD2(s0, qa.x, a2p[2 * v + 0]);
            FADD2(s1, qa.y, a2p[2 * v + 1]);
            float2 f0 = unpack2(s0), f1 = unpack2(s1);
            s0 = pack2(fmaxf(f0.x, 0.0f), fmaxf(f0.y, 0.0f));
            s1 = pack2(fmaxf(f1.x, 0.0f), fmaxf(f1.y, 0.0f));
            FFMA2(acc0, s0, wv.x);
            FFMA2(acc1, s1, wv.y);
        }
        float2 r0 = unpack2(acc0), r1 = unpack2(acc1);
        out[(long)(m0 + m) * 1024 + n] = (r0.x + r0.y) + (r1.x + r1.y);
    }
}

// ---------------------------------------------------------------------------
extern "C" void kernel_launch(void* const* d_in, const int* in_sizes, int n_in,
                              void* d_out, int out_size)
{
    const float* feature = (const float*)d_in[0];
    const int*   idx1    = (const int*)  d_in[1];
    const int*   idx2    = (const int*)  d_in[2];
    const float* w1      = (const float*)d_in[3];
    const float* b1      = (const float*)d_in[4];
    const float* w2      = (const float*)d_in[5];
    const float* b2      = (const float*)d_in[6];
    const float* w3      = (const float*)d_in[7];
    const float* b3      = (const float*)d_in[8];
    const float* w4      = (const float*)d_in[9];
    const float* b4      = (const float*)d_in[10];
    float* out = (float*)d_out;

    project_kernel<<<(2 * NPTS) / CPB, 512>>>(feature, idx1, idx2,
                                              w1, b1, w2, b2, w3, b3);
    dim3 grid2(NPTS / 256, NPTS / 16);
    pair_kernel<<<grid2, 256>>>(w4, b4, out);
}

// round 14
// speedup vs baseline: 1.1159x; 1.1159x over previous
#include <cuda_runtime.h>
#include <cuda_bf16.h>

#define CCH   256
#define HH    360
#define WW    360
#define NPTS  1024
#define CPB   16
#define NPAIR (CPB / 2)   // 8 center pairs per block

typedef unsigned long long ull;

// Scratch: a1[m][k] = f1 @ w3 ; a2p[n][k] = b3[k] - (f2 @ w3)[n][k]
__device__ float g_a1[NPTS * 32];
__device__ float g_a2p[NPTS * 32];

#define FFMA2(acc, x, w) \
    asm("fma.rn.f32x2 %0, %1, %2, %0;" : "+l"(acc) : "l"(x), "l"(w))
#define FADD2(d, a, b) \
    asm("add.rn.f32x2 %0, %1, %2;" : "=l"(d) : "l"(a), "l"(b))

__device__ __forceinline__ ull pack2(float a, float b) {
    ull r;
    asm("mov.b64 %0, {%1, %2};" : "=l"(r) : "f"(a), "f"(b));
    return r;
}
__device__ __forceinline__ float2 unpack2(ull v) {
    float2 f;
    asm("mov.b64 {%0, %1}, %2;" : "=f"(f.x), "=f"(f.y) : "l"(v));
    return f;
}

// ---------------------------------------------------------------------------
// Kernel 1: gather + 256->256->128 MLP (relu) + @w3 projection (b3 folded).
// 16 centers per block (8 f32x2 center-pairs), 512 threads, 128 blocks.
// Split-K partial sums. REVERTED to the r8 structure (best measured):
// plain LDG weights (cp.async pipeline measured slower), no prefetch.
// Shared memory (48KB, overlaid):
//   smemA: xs2[8][256]  -> w3s[128*32] after layer1
//   smemB: part1[8][256] -> part2[8][128] | h2p[8][128]
//   smemC: h1p[8][256]
// ---------------------------------------------------------------------------
__global__ __launch_bounds__(512) void project_kernel(
    const float* __restrict__ feature,
    const int*   __restrict__ idx1,
    const int*   __restrict__ idx2,
    const float* __restrict__ w1, const float* __restrict__ b1,
    const float* __restrict__ w2, const float* __restrict__ b2,
    const float* __restrict__ w3, const float* __restrict__ b3)
{
    __shared__ float2 smemA[NPAIR * 256];   // 16KB
    __shared__ float2 smemB[NPAIR * 256];   // 16KB
    __shared__ float2 smemC[NPAIR * 256];   // 16KB

    float2 (*xs2)[256] = (float2 (*)[256])smemA;
    float*  w3s        = (float*)smemA;
    float2 (*part1)[256] = (float2 (*)[256])smemB;
    float2* part2      = smemB;              // [8][128] float2 = 8KB
    float2 (*h2p)[128] = (float2 (*)[128])(smemB + 1024); // 8KB
    float2 (*h1p)[256] = (float2 (*)[256])smemC;

    const int tid = threadIdx.x;
    const int g0  = blockIdx.x * CPB;
    const bool frame2 = (g0 >= NPTS);
    const int* __restrict__ idx = frame2 ? idx2 : idx1;
    const int  i0 = frame2 ? (g0 - NPTS) : g0;

    // ---- gather: 16 centers x 256 channels = 4096 loads over 512 threads
    #pragma unroll
    for (int i = 0; i < 8; i++) {
        int e  = tid + i * 512;
        int t  = e >> 8;
        int ch = e & 255;
        int b  = __ldg(&idx[i0 + t]);
        int hh = __ldg(&idx[NPTS + i0 + t]);
        int ww = __ldg(&idx[2 * NPTS + i0 + t]);
        long off = (((long)b * CCH + ch) * HH + hh) * (long)WW + ww;
        ((float*)&xs2[t >> 1][ch])[t & 1] = __ldg(&feature[off]);
    }
    __syncthreads();

    // ---- layer 1: h1 = relu(x @ w1 + b1)
    {
        const int j = tid & 255;
        const int h = tid >> 8;
        const int cbase = h * 128;
        ull acc[NPAIR];
        {
            ull init;
            if (h) init = 0ULL;
            else { float bb = b1[j]; init = pack2(bb, bb); }
            #pragma unroll
            for (int p = 0; p < NPAIR; p++) acc[p] = init;
        }
        #pragma unroll 2
        for (int c0 = 0; c0 < 128; c0 += 4) {
            int c = cbase + c0;
            float v0 = w1[(c + 0) * 256 + j];
            float v1 = w1[(c + 1) * 256 + j];
            float v2 = w1[(c + 2) * 256 + j];
            float v3 = w1[(c + 3) * 256 + j];
            ull p0 = pack2(v0, v0), p1 = pack2(v1, v1);
            ull p2 = pack2(v2, v2), p3 = pack2(v3, v3);
            #pragma unroll
            for (int p = 0; p < NPAIR; p++) {
                ulonglong2 qa = *(const ulonglong2*)&xs2[p][c];
                ulonglong2 qb = *(const ulonglong2*)&xs2[p][c + 2];
                FFMA2(acc[p], qa.x, p0);
                FFMA2(acc[p], qa.y, p1);
                FFMA2(acc[p], qb.x, p2);
                FFMA2(acc[p], qb.y, p3);
            }
        }
        if (h) {
            #pragma unroll
            for (int p = 0; p < NPAIR; p++)
                part1[p][j] = unpack2(acc[p]);
        }
        __syncthreads();   // xs2 dead; part1 ready
        if (!h) {
            #pragma unroll
            for (int p = 0; p < NPAIR; p++) {
                float2 f = unpack2(acc[p]);
                float2 g = part1[p][j];
                h1p[p][j] = make_float2(fmaxf(f.x + g.x, 0.0f),
                                        fmaxf(f.y + g.y, 0.0f));
            }
        } else {
            // h==1 threads stage w3 into the freed xs2 region
            const float4* src = (const float4*)w3;
            float4* dst = (float4*)w3s;
            int l = tid - 256;
            #pragma unroll
            for (int i = 0; i < 4; i++) dst[l + i * 256] = src[l + i * 256];
        }
    }
    __syncthreads();

    // ---- layer 2: h2 = relu(h1 @ w2 + b2)
    {
        const int j2 = tid & 127;
        const int q  = tid >> 7;
        const int qc = q & 1;
        const int qp = q >> 1;
        const int cbase = qc * 128;
        const int pb = qp * 4;
        ull acc[4];
        {
            ull init;
            if (qc) init = 0ULL;
            else { float bb = b2[j2]; init = pack2(bb, bb); }
            #pragma unroll
            for (int u = 0; u < 4; u++) acc[u] = init;
        }
        #pragma unroll 2
        for (int c0 = 0; c0 < 128; c0 += 4) {
            int c = cbase + c0;
            float v0 = w2[(c + 0) * 128 + j2];
            float v1 = w2[(c + 1) * 128 + j2];
            float v2 = w2[(c + 2) * 128 + j2];
            float v3 = w2[(c + 3) * 128 + j2];
            ull p0 = pack2(v0, v0), p1 = pack2(v1, v1);
            ull p2 = pack2(v2, v2), p3 = pack2(v3, v3);
            #pragma unroll
            for (int u = 0; u < 4; u++) {
                int p = pb + u;
                ulonglong2 qa = *(const ulonglong2*)&h1p[p][c];
                ulonglong2 qb = *(const ulonglong2*)&h1p[p][c + 2];
                FFMA2(acc[u], qa.x, p0);
                FFMA2(acc[u], qa.y, p1);
                FFMA2(acc[u], qb.x, p2);
                FFMA2(acc[u], qb.y, p3);
            }
        }
        if (qc) {
            #pragma unroll
            for (int u = 0; u < 4; u++)
                part2[(qp * 4 + u) * 128 + j2] = unpack2(acc[u]);
        }
        __syncthreads();   // part1 dead; part2 ready
        if (!qc) {
            #pragma unroll
            for (int u = 0; u < 4; u++) {
                float2 f = unpack2(acc[u]);
                float2 g = part2[(qp * 4 + u) * 128 + j2];
                h2p[pb + u][j2] = make_float2(fmaxf(f.x + g.x, 0.0f),
                                              fmaxf(f.y + g.y, 0.0f));
            }
        }
    }
    __syncthreads();

    // ---- layer 3 (projection): a = h2 @ w3, b3 folded for frame 2.
    {
        const int w = tid >> 5;       // 0..15 = center
        const int k = tid & 31;
        const int p = w >> 1;
        const int hl = w & 1;
        float acc0 = 0.0f, acc1 = 0.0f, acc2 = 0.0f, acc3 = 0.0f;
        #pragma unroll 8
        for (int d = 0; d < 128; d += 4) {
            float hv0 = ((const float*)&h2p[p][d + 0])[hl];
            float hv1 = ((const float*)&h2p[p][d + 1])[hl];
            float hv2 = ((const float*)&h2p[p][d + 2])[hl];
            float hv3 = ((const float*)&h2p[p][d + 3])[hl];
            acc0 = fmaf(hv0, w3s[(d + 0) * 32 + k], acc0);
            acc1 = fmaf(hv1, w3s[(d + 1) * 32 + k], acc1);
            acc2 = fmaf(hv2, w3s[(d + 2) * 32 + k], acc2);
            acc3 = fmaf(hv3, w3s[(d + 3) * 32 + k], acc3);
        }
        float r = (acc0 + acc1) + (acc2 + acc3);
        int gg = g0 + w;
        if (!frame2) {
            g_a1[gg * 32 + k] = r;
        } else {
            g_a2p[(gg - NPTS) * 32 + k] = b3[k] - r;
        }
    }
}

// ---------------------------------------------------------------------------
// Kernel 2: out[m,n] = b4 + sum_k relu(a1[m,k] + a2p[n,k]) * w4[k]
// 256 threads (each owns one n), m-tile 16, grid (4, 64) = 256 CTAs.
// LOOP INTERCHANGE: k-chunks outer, m inner, acc[16] in registers.
// a2p/w4 now live only per-chunk -> much lower register pressure.
// ---------------------------------------------------------------------------
__global__ __launch_bounds__(256) void pair_kernel(
    const float* __restrict__ w4,
    const float* __restrict__ b4,
    float*       __restrict__ out)
{
    __shared__ float a1s[16 * 32];   // 2KB
    __shared__ float2 w4s[16];       // 128B: packed (w4[2i], w4[2i+1]) pairs

    const int tid = threadIdx.x;
    const int n   = blockIdx.x * 256 + tid;
    const int m0  = blockIdx.y * 16;

    // stage a1 tile (16 x 32 = 512 floats) via float4
    if (tid < 128)
        ((float4*)a1s)[tid] = ((const float4*)(g_a1 + m0 * 32))[tid];
    // stage w4 pairs
    if (tid < 16)
        w4s[tid] = ((const float2*)w4)[tid];

    const float bias = b4[0];
    const float4* a2row = (const float4*)(g_a2p + (long)n * 32);
    __syncthreads();

    // accumulators: one packed f32x2 per m-row
    ull acc[16];
    {
        ull init = pack2(bias, 0.0f);
        #pragma unroll
        for (int m = 0; m < 16; m++) acc[m] = init;
    }

    #pragma unroll 1
    for (int v = 0; v < 8; v++) {          // 8 chunks of 4 dims
        float4 av = a2row[v];              // this thread's a2p chunk (L1 hot)
        ull a2p0 = pack2(av.x, av.y);
        ull a2p1 = pack2(av.z, av.w);
        ulonglong2 wv = ((const ulonglong2*)w4s)[v];   // broadcast
        #pragma unroll
        for (int m = 0; m < 16; m++) {
            ulonglong2 qa = *(const ulonglong2*)&a1s[m * 32 + 4 * v];
            ull s0, s1;
            FADD2(s0, qa.x, a2p0);
            FADD2(s1, qa.y, a2p1);
            float2 f0 = unpack2(s0), f1 = unpack2(s1);
            s0 = pack2(fmaxf(f0.x, 0.0f), fmaxf(f0.y, 0.0f));
            s1 = pack2(fmaxf(f1.x, 0.0f), fmaxf(f1.y, 0.0f));
            FFMA2(acc[m], s0, wv.x);
            FFMA2(acc[m], s1, wv.y);
        }
    }

    #pragma unroll
    for (int m = 0; m < 16; m++) {
        float2 r = unpack2(acc[m]);
        out[(long)(m0 + m) * 1024 + n] = r.x + r.y;
    }
}

// ---------------------------------------------------------------------------
extern "C" void kernel_launch(void* const* d_in, const int* in_sizes, int n_in,
                              void* d_out, int out_size)
{
    const float* feature = (const float*)d_in[0];
    const int*   idx1    = (const int*)  d_in[1];
    const int*   idx2    = (const int*)  d_in[2];
    const float* w1      = (const float*)d_in[3];
    const float* b1      = (const float*)d_in[4];
    const float* w2      = (const float*)d_in[5];
    const float* b2      = (const float*)d_in[6];
    const float* w3      = (const float*)d_in[7];
    const float* b3      = (const float*)d_in[8];
    const float* w4      = (const float*)d_in[9];
    const float* b4      = (const float*)d_in[10];
    float* out = (float*)d_out;

    project_kernel<<<(2 * NPTS) / CPB, 512>>>(feature, idx1, idx2,
                                              w1, b1, w2, b2, w3, b3);
    dim3 grid2(NPTS / 256, NPTS / 16);
    pair_kernel<<<grid2, 256>>>(w4, b4, out);
}